// round 1
// baseline (speedup 1.0000x reference)
#include <cuda_runtime.h>

// ---------------------------------------------------------------------------
// AFNO2D: rfft2(128x128, ortho) -> blockwise complex MLP (8 blocks x 96ch,
// relu, softshrink 0.01) -> irfft2 -> + x.
// Pipeline: K1 rfftW  x->A ; K2 fftH A->B (*1/128) ; K3 MLP B->A ;
//           K4 ifftH A->B ; K5 irfftW B (+x, *1/128) -> out
// ---------------------------------------------------------------------------

#define BB 4
#define HH 128
#define WW 128
#define CH 768
#define NB 8
#define BS 96
#define WF 65
#define MPTS (BB*HH*WF)   /* 33280 frequency points */

// scratch (device globals: allocation-free)
__device__ float2 g_A[(size_t)MPTS * CH];
__device__ float2 g_B[(size_t)MPTS * CH];

typedef unsigned long long u64;

__device__ __forceinline__ int brev7(int j) { return (int)(__brev((unsigned)j) >> 25); }

__device__ __forceinline__ u64 pk2(float a, float b) {
    u64 r; asm("mov.b64 %0,{%1,%2};" : "=l"(r) : "f"(a), "f"(b)); return r;
}
__device__ __forceinline__ void unpk2(u64 v, float& a, float& b) {
    asm("mov.b64 {%0,%1},%2;" : "=f"(a), "=f"(b) : "l"(v));
}
__device__ __forceinline__ u64 ffma2(u64 a, u64 b, u64 c) {
    u64 d; asm("fma.rn.f32x2 %0,%1,%2,%3;" : "=l"(d) : "l"(a), "l"(b), "l"(c)); return d;
}

// ---------------------------------------------------------------------------
// per-thread iterative radix-2 FFT, N=128, data in smem row (stride 1),
// twiddles twc[j]=cos(2pi j/128), tws[j]=sin(2pi j/128); dir=-1 fwd, +1 inv.
// Input must be placed in bit-reversed order.
// ---------------------------------------------------------------------------
__device__ __forceinline__ void fft128(float* re, float* im,
                                       const float* twc, const float* tws, float dir)
{
    #pragma unroll
    for (int s = 1; s <= 7; s++) {
        const int half  = 1 << (s - 1);
        const int tstep = 128 >> s;
        for (int j0 = 0; j0 < 128; j0 += (half << 1)) {
            for (int j = 0; j < half; j++) {
                float wr = twc[j * tstep];
                float wi = dir * tws[j * tstep];
                int a = j0 + j, b = a + half;
                float br = re[b], bi = im[b];
                float tr = br * wr - bi * wi;
                float ti = br * wi + bi * wr;
                float ar = re[a], ai = im[a];
                re[b] = ar - tr; im[b] = ai - ti;
                re[a] = ar + tr; im[a] = ai + ti;
            }
        }
    }
}

#define FFT_PITCH 129

// ---------------- K1: rfft along W: x -> g_A[b,h,wf,c] ---------------------
__global__ void k1_rfft_w(const float* __restrict__ x)
{
    __shared__ float sre[32 * FFT_PITCH], sim[32 * FFT_PITCH];
    __shared__ float twc[64], tws[64];
    int t = threadIdx.x;
    for (int j = t; j < 64; j += 32) {
        float s, c; sincospif(j * (1.0f / 64.0f), &s, &c);
        twc[j] = c; tws[j] = s;
    }
    int bh = blockIdx.y;                 // b*128+h
    int c0 = blockIdx.x * 32 + t;
    float* re = &sre[t * FFT_PITCH];
    float* im = &sim[t * FFT_PITCH];

    const float* px = x + (size_t)bh * WW * CH + c0;
    for (int w = 0; w < 128; w++) re[brev7(w)] = px[(size_t)w * CH];
    for (int w = 0; w < 128; w++) im[w] = 0.0f;
    __syncthreads();

    fft128(re, im, twc, tws, -1.0f);

    float2* pa = g_A + (size_t)bh * WF * CH + c0;
    for (int k = 0; k <= 64; k++) pa[(size_t)k * CH] = make_float2(re[k], im[k]);
}

// ---------------- K2: fft along H: g_A -> g_B, scale 1/128 -----------------
__global__ void k2_fft_h()
{
    __shared__ float sre[32 * FFT_PITCH], sim[32 * FFT_PITCH];
    __shared__ float twc[64], tws[64];
    int t = threadIdx.x;
    for (int j = t; j < 64; j += 32) {
        float s, c; sincospif(j * (1.0f / 64.0f), &s, &c);
        twc[j] = c; tws[j] = s;
    }
    int bwf = blockIdx.y;               // b*65 + wf
    int b  = bwf / WF;
    int wf = bwf - b * WF;
    int c0 = blockIdx.x * 32 + t;
    float* re = &sre[t * FFT_PITCH];
    float* im = &sim[t * FFT_PITCH];

    const float2* pa = g_A + ((size_t)b * HH * WF + wf) * CH + c0;
    for (int h = 0; h < 128; h++) {
        float2 v = pa[(size_t)h * WF * CH];
        int p = brev7(h);
        re[p] = v.x; im[p] = v.y;
    }
    __syncthreads();

    fft128(re, im, twc, tws, -1.0f);

    float2* pb = g_B + ((size_t)b * HH * WF + wf) * CH + c0;
    const float sc = 1.0f / 128.0f;
    for (int h = 0; h < 128; h++)
        pb[(size_t)h * WF * CH] = make_float2(re[h] * sc, im[h] * sc);
}

// ---------------- K3: blockwise complex MLP: g_B -> g_A --------------------
// block = (channel-block n, tile of 32 freq points); 96 threads (one per out ch)
__global__ void __launch_bounds__(96) k3_mlp(const float* __restrict__ w1,
                                             const float* __restrict__ b1,
                                             const float* __restrict__ w2,
                                             const float* __restrict__ b2)
{
    __shared__ float2 sx[32][BS];
    const int o  = threadIdx.x;           // 0..95
    const int n  = blockIdx.x;            // 0..7
    const int m0 = blockIdx.y * 32;

    // load x tile (rows are contiguous rows of g_B)
    for (int idx = o; idx < 32 * BS; idx += BS) {
        int p = idx / BS, i = idx - p * BS;
        sx[p][i] = g_B[(size_t)(m0 + p) * CH + n * BS + i];
    }
    __syncthreads();

    // ---- layer 1: o1 = relu(x W1 + b1), complex (W = w1[0] + i w1[1]) -----
    const float* w1r = w1 + (size_t)n * BS * BS;
    const float* w1i = w1 + (size_t)(NB + n) * BS * BS;
    u64 acc[32];
    {
        float bre = b1[n * BS + o];
        float bim = b1[NB * BS + n * BS + o];
        u64 binit = pk2(bre, bim);
        #pragma unroll
        for (int p = 0; p < 32; p++) acc[p] = binit;
    }
    for (int i = 0; i < BS; i++) {
        float wr = w1r[i * BS + o];
        float wi = w1i[i * BS + o];
        u64 wri = pk2(wr, wi);
        u64 wir = pk2(-wi, wr);
        #pragma unroll
        for (int p = 0; p < 32; p++) {
            float2 xv = sx[p][i];
            acc[p] = ffma2(pk2(xv.x, xv.x), wri, acc[p]);
            acc[p] = ffma2(pk2(xv.y, xv.y), wir, acc[p]);
        }
    }
    __syncthreads();
    #pragma unroll
    for (int p = 0; p < 32; p++) {
        float r, ii; unpk2(acc[p], r, ii);
        sx[p][o] = make_float2(fmaxf(r, 0.0f), fmaxf(ii, 0.0f));
    }
    __syncthreads();

    // ---- layer 2: o2 = o1 W2 + b2, softshrink --------------------------
    const float* w2r = w2 + (size_t)n * BS * BS;
    const float* w2i = w2 + (size_t)(NB + n) * BS * BS;
    {
        float bre = b2[n * BS + o];
        float bim = b2[NB * BS + n * BS + o];
        u64 binit = pk2(bre, bim);
        #pragma unroll
        for (int p = 0; p < 32; p++) acc[p] = binit;
    }
    for (int i = 0; i < BS; i++) {
        float wr = w2r[i * BS + o];
        float wi = w2i[i * BS + o];
        u64 wri = pk2(wr, wi);
        u64 wir = pk2(-wi, wr);
        #pragma unroll
        for (int p = 0; p < 32; p++) {
            float2 xv = sx[p][i];
            acc[p] = ffma2(pk2(xv.x, xv.x), wri, acc[p]);
            acc[p] = ffma2(pk2(xv.y, xv.y), wir, acc[p]);
        }
    }
    const float lam = 0.01f;
    #pragma unroll
    for (int p = 0; p < 32; p++) {
        float r, ii; unpk2(acc[p], r, ii);
        r  = copysignf(fmaxf(fabsf(r)  - lam, 0.0f), r);
        ii = copysignf(fmaxf(fabsf(ii) - lam, 0.0f), ii);
        g_A[(size_t)(m0 + p) * CH + n * BS + o] = make_float2(r, ii);
    }
}

// ---------------- K4: inverse fft along H: g_A -> g_B ----------------------
__global__ void k4_ifft_h()
{
    __shared__ float sre[32 * FFT_PITCH], sim[32 * FFT_PITCH];
    __shared__ float twc[64], tws[64];
    int t = threadIdx.x;
    for (int j = t; j < 64; j += 32) {
        float s, c; sincospif(j * (1.0f / 64.0f), &s, &c);
        twc[j] = c; tws[j] = s;
    }
    int bwf = blockIdx.y;
    int b  = bwf / WF;
    int wf = bwf - b * WF;
    int c0 = blockIdx.x * 32 + t;
    float* re = &sre[t * FFT_PITCH];
    float* im = &sim[t * FFT_PITCH];

    const float2* pa = g_A + ((size_t)b * HH * WF + wf) * CH + c0;
    for (int h = 0; h < 128; h++) {
        float2 v = pa[(size_t)h * WF * CH];
        int p = brev7(h);
        re[p] = v.x; im[p] = v.y;
    }
    __syncthreads();

    fft128(re, im, twc, tws, +1.0f);

    float2* pb = g_B + ((size_t)b * HH * WF + wf) * CH + c0;
    for (int h = 0; h < 128; h++)
        pb[(size_t)h * WF * CH] = make_float2(re[h], im[h]);
}

// ---------- K5: inverse rfft along W (+ residual, *1/128): g_B,x -> out ----
__global__ void k5_irfft_w(const float* __restrict__ x, float* __restrict__ out)
{
    __shared__ float sre[32 * FFT_PITCH], sim[32 * FFT_PITCH];
    __shared__ float twc[64], tws[64];
    int t = threadIdx.x;
    for (int j = t; j < 64; j += 32) {
        float s, c; sincospif(j * (1.0f / 64.0f), &s, &c);
        twc[j] = c; tws[j] = s;
    }
    int bh = blockIdx.y;
    int c0 = blockIdx.x * 32 + t;
    float* re = &sre[t * FFT_PITCH];
    float* im = &sim[t * FFT_PITCH];

    const float2* pb = g_B + (size_t)bh * WF * CH + c0;
    for (int k = 0; k <= 64; k++) {
        float2 v = pb[(size_t)k * CH];
        int p = brev7(k);
        re[p] = v.x; im[p] = v.y;
        if (k >= 1 && k <= 63) {        // Hermitian completion
            int q = brev7(128 - k);
            re[q] = v.x; im[q] = -v.y;
        }
    }
    __syncthreads();

    fft128(re, im, twc, tws, +1.0f);

    const float* px = x   + (size_t)bh * WW * CH + c0;
    float*       po = out + (size_t)bh * WW * CH + c0;
    const float sc = 1.0f / 128.0f;
    for (int w = 0; w < 128; w++)
        po[(size_t)w * CH] = fmaf(re[w], sc, px[(size_t)w * CH]);
}

// ---------------------------------------------------------------------------
extern "C" void kernel_launch(void* const* d_in, const int* in_sizes, int n_in,
                              void* d_out, int out_size)
{
    (void)in_sizes; (void)n_in; (void)out_size;
    const float* x  = (const float*)d_in[0];
    const float* w1 = (const float*)d_in[1];
    const float* b1 = (const float*)d_in[2];
    const float* w2 = (const float*)d_in[3];
    const float* b2 = (const float*)d_in[4];
    float* out = (float*)d_out;

    k1_rfft_w <<<dim3(CH / 32, BB * HH), 32>>>(x);
    k2_fft_h  <<<dim3(CH / 32, BB * WF), 32>>>();
    k3_mlp    <<<dim3(NB, MPTS / 32), 96>>>(w1, b1, w2, b2);
    k4_ifft_h <<<dim3(CH / 32, BB * WF), 32>>>();
    k5_irfft_w<<<dim3(CH / 32, BB * HH), 32>>>(x, out);
}